// round 15
// baseline (speedup 1.0000x reference)
#include <cuda_runtime.h>
#include <cuda_fp16.h>
#include <cstdint>
#include <math.h>

#define Bq 4
#define Hh 16
#define Ss 4096
#define Dd 128
#define Mm 128
#define BH (Bq*Hh)
#define EPSV 1e-6f

// Scratch (zero at first load; every execution re-zeroes g_S/g_w in k_transS)
__device__ float g_S [BH*Dd*Mm];  // S accumulation (WITHOUT S_prev), zero-based
__device__ float g_ST[BH*Dd*Mm];  // S_t transposed [BH, M, D] (fp32)
__device__ float g_w [BH*Dd];     // sum_s phi(k)[s,d] accumulation, zero-based
__device__ float g_w2[BH*Dd];     // final w[d] = Ss*z_prev[d] + g_w[d]

__device__ __forceinline__ float phi(float x) {
    return x > 0.f ? x + 1.f : expf(x);
}
__device__ __forceinline__ unsigned packh2(float lo, float hi) {
    unsigned r;
    asm("cvt.rn.f16x2.f32 %0, %1, %2;" : "=r"(r) : "f"(hi), "f"(lo));
    return r;
}
__device__ __forceinline__ unsigned s2u(const void* p) {
    unsigned a;
    asm("{ .reg .u64 t; cvta.to.shared.u64 t, %1; cvt.u32.u64 %0, t; }"
        : "=r"(a) : "l"(p));
    return a;
}
__device__ __forceinline__ void mma16(float* c, const unsigned* a,
                                      unsigned b0, unsigned b1) {
    asm volatile(
        "mma.sync.aligned.m16n8k16.row.col.f32.f16.f16.f32 "
        "{%0,%1,%2,%3}, {%4,%5,%6,%7}, {%8,%9}, {%0,%1,%2,%3};"
        : "+f"(c[0]), "+f"(c[1]), "+f"(c[2]), "+f"(c[3])
        : "r"(a[0]), "r"(a[1]), "r"(a[2]), "r"(a[3]), "r"(b0), "r"(b1));
}
__device__ __forceinline__ void ldsm4(unsigned* r, unsigned a) {
    asm volatile("ldmatrix.sync.aligned.m8n8.x4.shared.b16 {%0,%1,%2,%3}, [%4];"
        : "=r"(r[0]), "=r"(r[1]), "=r"(r[2]), "=r"(r[3]) : "r"(a));
}
__device__ __forceinline__ void ldsm4t(unsigned* r, unsigned a) {
    asm volatile("ldmatrix.sync.aligned.m8n8.x4.trans.shared.b16 {%0,%1,%2,%3}, [%4];"
        : "=r"(r[0]), "=r"(r[1]), "=r"(r[2]), "=r"(r[3]) : "r"(a));
}

// ---------------------------------------------------------------------------
// Kernel 1 (fp16 + ldmatrix.trans, 256 thr, 2 CTAs/SM, m-split):
//   CTA computes 128d x 64m of g_S for one 512-s chunk.
//   grid (16, BH): bx>>1 = chunk, bx&1 = m-half. Paired CTAs share k via L2.
//   mhalf==0 CTA also emits ksum and fused z_t.
// ---------------------------------------------------------------------------
#define P1_CHUNK 512
#define P1S 32
#define KP 68                           // k tile row pitch (words)
#define VP 36                           // v tile row pitch (words)
#define KTW (P1S*KP)                    // 2176
#define VTW (P1S*VP)                    // 1152
#define P1NST (P1_CHUNK/P1S)            // 16
#define P1_SMEM_BYTES (2*(KTW+VTW)*4)   // 26624 B

__global__ void __launch_bounds__(256, 2)
k_phase1(const float* __restrict__ kk, const float* __restrict__ vv,
         const float* __restrict__ mask, const float* __restrict__ z_prev,
         float* __restrict__ ztp) {
    extern __shared__ unsigned dyn1[];
    __shared__ float zps[Dd];
    __shared__ float ksum_sm[16][Dd];    // 8 KB

    int head = blockIdx.y;
    int bx = blockIdx.x;
    int chunk = bx >> 1, mhalf = bx & 1;
    int sbase = chunk * P1_CHUNK;
    int m_off = mhalf * 64;
    int tid = threadIdx.x;
    int warp = tid >> 5, lane = tid & 31;
    int gid = lane >> 2, tig = lane & 3;
    int d0w = (warp >> 1) * 32;          // 4 d-groups
    int m0w = (warp & 1) * 32;           // 2 m-groups (local, 64 wide)

    // staging maps
    int rt = tid >> 4;                   // k rows rt, rt+16
    int dcol = (tid & 15) * 8;           // 8 d per thread
    int rv = tid >> 3;                   // v row
    int mcol = (tid & 7) * 8;            // 8 m per thread

    if (tid < Dd) zps[tid] = z_prev[head * Dd + tid];

    unsigned* kbuf[2] = { dyn1, dyn1 + (KTW + VTW) };
    unsigned* vbuf[2] = { dyn1 + KTW, dyn1 + (KTW + VTW) + KTW };

    int lrow = (lane & 7) + ((lane >> 4) & 1) * 8;
    int csel = ((lane >> 3) & 1) * 16;
    int aOffB = lrow * (KP * 4) + d0w * 2 + csel;
    int bOffB = lrow * (VP * 4) + m0w * 2 + csel;
    unsigned kaddr[2] = { s2u(kbuf[0]), s2u(kbuf[1]) };
    unsigned vaddr[2] = { s2u(vbuf[0]), s2u(vbuf[1]) };

    float kacc[8];
#pragma unroll
    for (int j = 0; j < 8; j++) kacc[j] = 0.f;
    float acc[2][4][4];
#pragma unroll
    for (int ah = 0; ah < 2; ah++)
#pragma unroll
        for (int bi = 0; bi < 4; bi++)
#pragma unroll
            for (int t = 0; t < 4; t++) acc[ah][bi][t] = 0.f;

    const float* kh = kk + (size_t)head * Ss * Dd;
    const float* vh = vv + (size_t)head * Ss * Mm + m_off;
    const float* mh = mask + (size_t)head * Ss;
    float* zth = (ztp && mhalf == 0) ? (ztp + (size_t)head * Dd * Ss) : (float*)0;

    float4 k0a, k0b, k1a, k1b, v0a, v0b;
    float msk0, msk1, mskv;
    {
        int s0 = sbase + rt, s1 = sbase + rt + 16, sv = sbase + rv;
        k0a = *(const float4*)(kh + (size_t)s0 * Dd + dcol);
        k0b = *(const float4*)(kh + (size_t)s0 * Dd + dcol + 4);
        k1a = *(const float4*)(kh + (size_t)s1 * Dd + dcol);
        k1b = *(const float4*)(kh + (size_t)s1 * Dd + dcol + 4);
        v0a = *(const float4*)(vh + (size_t)sv * Mm + mcol);
        v0b = *(const float4*)(vh + (size_t)sv * Mm + mcol + 4);
        msk0 = mh[s0]; msk1 = mh[s1]; mskv = mh[sv];
    }

    for (int t = 0; t < P1NST; t++) {
        int b = t & 1;
        float kv0[8], kv1[8], va[8];
        kv0[0]=phi(k0a.x)*msk0; kv0[1]=phi(k0a.y)*msk0; kv0[2]=phi(k0a.z)*msk0; kv0[3]=phi(k0a.w)*msk0;
        kv0[4]=phi(k0b.x)*msk0; kv0[5]=phi(k0b.y)*msk0; kv0[6]=phi(k0b.z)*msk0; kv0[7]=phi(k0b.w)*msk0;
        kv1[0]=phi(k1a.x)*msk1; kv1[1]=phi(k1a.y)*msk1; kv1[2]=phi(k1a.z)*msk1; kv1[3]=phi(k1a.w)*msk1;
        kv1[4]=phi(k1b.x)*msk1; kv1[5]=phi(k1b.y)*msk1; kv1[6]=phi(k1b.z)*msk1; kv1[7]=phi(k1b.w)*msk1;
        va[0]=v0a.x*mskv; va[1]=v0a.y*mskv; va[2]=v0a.z*mskv; va[3]=v0a.w*mskv;
        va[4]=v0b.x*mskv; va[5]=v0b.y*mskv; va[6]=v0b.z*mskv; va[7]=v0b.w*mskv;
#pragma unroll
        for (int j = 0; j < 8; j++) kacc[j] += kv0[j] + kv1[j];
        {
            uint4 p0 = make_uint4(packh2(kv0[0], kv0[1]), packh2(kv0[2], kv0[3]),
                                  packh2(kv0[4], kv0[5]), packh2(kv0[6], kv0[7]));
            uint4 p1 = make_uint4(packh2(kv1[0], kv1[1]), packh2(kv1[2], kv1[3]),
                                  packh2(kv1[4], kv1[5]), packh2(kv1[6], kv1[7]));
            uint4 pv = make_uint4(packh2(va[0], va[1]), packh2(va[2], va[3]),
                                  packh2(va[4], va[5]), packh2(va[6], va[7]));
            *(uint4*)&kbuf[b][rt * KP + (tid & 15) * 4] = p0;
            *(uint4*)&kbuf[b][(rt + 16) * KP + (tid & 15) * 4] = p1;
            *(uint4*)&vbuf[b][rv * VP + (tid & 7) * 4] = pv;
        }

        if (t + 1 < P1NST) {   // batched coalesced prefetch, hidden by MMA
            int s0 = sbase + (t + 1) * P1S + rt;
            int s1 = s0 + 16;
            int sv = sbase + (t + 1) * P1S + rv;
            k0a = *(const float4*)(kh + (size_t)s0 * Dd + dcol);
            k0b = *(const float4*)(kh + (size_t)s0 * Dd + dcol + 4);
            k1a = *(const float4*)(kh + (size_t)s1 * Dd + dcol);
            k1b = *(const float4*)(kh + (size_t)s1 * Dd + dcol + 4);
            v0a = *(const float4*)(vh + (size_t)sv * Mm + mcol);
            v0b = *(const float4*)(vh + (size_t)sv * Mm + mcol + 4);
            msk0 = mh[s0]; msk1 = mh[s1]; mskv = mh[sv];
        }
        __syncthreads();

        // fused z_t (mhalf==0 only): transposed smem read-back, 16 s per thread
        if (zth) {
            int dz = tid >> 1, szb = (tid & 1) * 16;
            const __half* khp = (const __half*)kbuf[b];
            float zp = zps[dz];
            float zf[16];
#pragma unroll
            for (int j = 0; j < 16; j++)
                zf[j] = __half2float(khp[(szb + j) * (KP * 2) + dz]) + zp;
            float* zr = zth + (size_t)dz * Ss + sbase + t * P1S + szb;
            *(float4*)zr        = make_float4(zf[0],  zf[1],  zf[2],  zf[3]);
            *(float4*)(zr + 4)  = make_float4(zf[4],  zf[5],  zf[6],  zf[7]);
            *(float4*)(zr + 8)  = make_float4(zf[8],  zf[9],  zf[10], zf[11]);
            *(float4*)(zr + 12) = make_float4(zf[12], zf[13], zf[14], zf[15]);
        }

#pragma unroll
        for (int ks = 0; ks < 2; ks++) {
            int soA = ks * 16 * KP * 4;
            int soB = ks * 16 * VP * 4;
            unsigned A0[4], A1[4], B0[4], B1[4];
            ldsm4t(A0, kaddr[b] + aOffB + soA);
            ldsm4t(A1, kaddr[b] + aOffB + soA + 32);   // d+16
            ldsm4t(B0, vaddr[b] + bOffB + soB);
            ldsm4t(B1, vaddr[b] + bOffB + soB + 32);   // m+16
#pragma unroll
            for (int ah = 0; ah < 2; ah++) {
                const unsigned* Aa = ah ? A1 : A0;
#pragma unroll
                for (int bi = 0; bi < 4; bi++) {
                    const unsigned* Bl = (bi >> 1) ? B1 : B0;
                    mma16(acc[ah][bi], Aa, Bl[bi & 1], Bl[(bi & 1) + 2]);
                }
            }
        }
    }

    float* Sg = g_S + (size_t)head * Dd * Mm;
#pragma unroll
    for (int ah = 0; ah < 2; ah++)
#pragma unroll
        for (int bi = 0; bi < 4; bi++) {
            int dr = d0w + ah * 16 + gid;
            int mc = m_off + m0w + bi * 8 + tig * 2;
            atomicAdd(&Sg[(size_t)dr * Mm + mc],       acc[ah][bi][0]);
            atomicAdd(&Sg[(size_t)dr * Mm + mc + 1],   acc[ah][bi][1]);
            atomicAdd(&Sg[(size_t)(dr+8) * Mm + mc],   acc[ah][bi][2]);
            atomicAdd(&Sg[(size_t)(dr+8) * Mm + mc+1], acc[ah][bi][3]);
        }

    // ksum (mhalf==0 only): smem matrix reduce, one atomic per d per CTA
#pragma unroll
    for (int j = 0; j < 8; j++) ksum_sm[rt][dcol + j] = kacc[j];
    __syncthreads();
    if (mhalf == 0 && tid < Dd) {
        float s = 0.f;
#pragma unroll 4
        for (int i = 0; i < 16; i++) s += ksum_sm[i][tid];
        atomicAdd(&g_w[head * Dd + tid], s);
    }
}

// ---------------------------------------------------------------------------
// Kernel 1b: S_t = g_S + S_prev -> (outS copy, g_ST transposed fp32),
// g_w2 = g_w + Ss*z_prev; re-zero g_S/g_w for next replay.
// ---------------------------------------------------------------------------
__global__ void k_transS(const float* __restrict__ S_prev,
                         const float* __restrict__ z_prev,
                         float* __restrict__ outS) {
    __shared__ float tile[32][33];
    int head = blockIdx.z;
    int db = blockIdx.x * 32, mb = blockIdx.y * 32;
    int tx = threadIdx.x, ty = threadIdx.y;
    float* Sg = g_S + (size_t)head * Dd * Mm;
    const float* Sp = S_prev + (size_t)head * Dd * Mm;
    float* STg = g_ST + (size_t)head * Dd * Mm;
    float* So = outS ? (outS + (size_t)head * Dd * Mm) : (float*)0;
    for (int r = ty; r < 32; r += 8) {
        size_t idx = (size_t)(db + r) * Mm + mb + tx;
        float val = Sg[idx] + Sp[idx];
        tile[r][tx] = val;
        if (So) So[idx] = val;
        Sg[idx] = 0.f;
    }
    if (blockIdx.x == 0 && blockIdx.y == 0) {
        int tid = ty * 32 + tx;
        if (tid < Dd) {
            g_w2[head * Dd + tid] = g_w[head * Dd + tid]
                                  + (float)Ss * z_prev[head * Dd + tid];
            g_w[head * Dd + tid] = 0.f;
        }
    }
    __syncthreads();
    for (int r = ty; r < 32; r += 8)
        STg[(size_t)(mb + r) * Dd + db + tx] = tile[tx][r];
}

// ---------------------------------------------------------------------------
// Kernel 2 (fp16 tensor, unchanged from R13/R14)
// ---------------------------------------------------------------------------
#define SQT 2048
#define NCH (SQT/128)
#define P2RW 68
#define P2BW (128*P2RW)
#define OFF_WS   (3*P2BW)
#define OFF_DENS (OFF_WS + 128)
#define SM2_WORDS (OFF_DENS + 256)
#define SM2_BYTES (SM2_WORDS * 4)

__global__ void __launch_bounds__(512, 1)
k_phase2(const float* __restrict__ qq, float* __restrict__ out) {
    extern __shared__ unsigned sm2[];
    unsigned* Ab[2] = { sm2, sm2 + P2BW };
    unsigned* Bb = sm2 + 2 * P2BW;
    float* ws   = (float*)(sm2 + OFF_WS);
    float* dens = (float*)(sm2 + OFF_DENS);   // [2][128]

    int head = blockIdx.y;
    int sbase = blockIdx.x * SQT;
    int tid = threadIdx.x;
    int warp = tid >> 5, lane = tid & 31;
    int gid = lane >> 2, tig = lane & 3;
    int sw = (warp >> 2) * 32;
    int m0 = (warp & 3) * 32;

    const float* qh  = qq + (size_t)head * Ss * Dd;
    const float* STg = g_ST + (size_t)head * Dd * Mm;

    if (tid < 128) ws[tid] = g_w2[head * Dd + tid];
    {
        const float* bp = STg + (size_t)warp * Dd + lane * 4;
#pragma unroll
        for (int i = 0; i < 8; i++) {
            float4 t4 = *(const float4*)(bp + (size_t)(16 * i) * Dd);
            int r = warp + 16 * i;
            unsigned* w = Bb + r * P2RW + lane * 2;
            w[0] = packh2(t4.x, t4.y);
            w[1] = packh2(t4.z, t4.w);
        }
    }
    __syncthreads();
    float4 wv4 = *(const float4*)(ws + lane * 4);

    {
        const float* qp = qh + (size_t)(sbase + warp) * Dd + lane * 4;
#pragma unroll
        for (int i = 0; i < 8; i++) {
            float4 qa = *(const float4*)(qp + (size_t)(16 * i) * Dd);
            float p0 = phi(qa.x), p1 = phi(qa.y), p2 = phi(qa.z), p3 = phi(qa.w);
            float ds = p0 * wv4.x + p1 * wv4.y + p2 * wv4.z + p3 * wv4.w;
            ds += __shfl_xor_sync(0xffffffffu, ds, 1);
            ds += __shfl_xor_sync(0xffffffffu, ds, 2);
            ds += __shfl_xor_sync(0xffffffffu, ds, 4);
            ds += __shfl_xor_sync(0xffffffffu, ds, 8);
            ds += __shfl_xor_sync(0xffffffffu, ds, 16);
            int r = warp + 16 * i;
            if (lane == 0) dens[r] = ds;
            unsigned* w = Ab[0] + r * P2RW + lane * 2;
            w[0] = packh2(p0, p1);
            w[1] = packh2(p2, p3);
        }
    }

    int sel = lane >> 3, lrow = lane & 7;
    int aOffB = 4 * ((sw + (sel & 1) * 8 + lrow) * P2RW + (sel >> 1) * 4);
    int bOffB = 4 * ((m0 + (sel & 1) * 8 + lrow) * P2RW + (sel >> 1) * 4);
    unsigned aBase[2] = { s2u(Ab[0]), s2u(Ab[1]) };
    unsigned bBase = s2u(Bb);
    const int ROW16 = 16 * P2RW * 4;

    for (int c = 0; c < NCH; c++) {
        int cb = c & 1, nb = cb ^ 1;
        bool more = (c + 1 < NCH);

        float4 qn[8];
        if (more) {
            const float* qp = qh + (size_t)(sbase + (c + 1) * 128 + warp) * Dd + lane * 4;
#pragma unroll
            for (int i = 0; i < 8; i++)
                qn[i] = *(const float4*)(qp + (size_t)(16 * i) * Dd);
        }
        __syncthreads();

        float acc[2][4][4];
#pragma unroll
        for (int ah = 0; ah < 2; ah++)
#pragma unroll
            for (int bi = 0; bi < 4; bi++)
#pragma unroll
                for (int t = 0; t < 4; t++) acc[ah][bi][t] = 0.f;

#pragma unroll
        for (int i = 0; i < 8; i++) {
            if (more && i >= 4) {
#pragma unroll
                for (int h = 0; h < 2; h++) {
                    int j = (i - 4) * 2 + h;
                    float p0 = phi(qn[j].x), p1 = phi(qn[j].y),
                          p2 = phi(qn[j].z), p3 = phi(qn[j].w);
                    float ds = p0 * wv4.x + p1 * wv4.y + p2 * wv4.z + p3 * wv4.w;
                    ds += __shfl_xor_sync(0xffffffffu, ds, 1);
                    ds += __shfl_xor_sync(0xffffffffu, ds, 2);
                    ds += __shfl_xor_sync(0xffffffffu, ds, 4);
                    ds += __shfl_xor_sync(0xffffffffu, ds, 8);
                    ds += __shfl_xor_sync(0xffffffffu, ds, 16);
                    int r = warp + 16 * j;
                    if (lane == 0) dens[nb * 128 + r] = ds;
                    unsigned* w = Ab[nb] + r * P2RW + lane * 2;
                    w[0] = packh2(p0, p1);
                    w[1] = packh2(p2, p3);
                }
            }
            unsigned A[2][4], B[2][4];
            ldsm4(A[0], aBase[cb] + aOffB + i * 32);
            ldsm4(A[1], aBase[cb] + aOffB + ROW16 + i * 32);
            ldsm4(B[0], bBase + bOffB + i * 32);
            ldsm4(B[1], bBase + bOffB + ROW16 + i * 32);
#pragma unroll
            for (int ah = 0; ah < 2; ah++)
#pragma unroll
                for (int bi = 0; bi < 4; bi++)
                    mma16(acc[ah][bi], A[ah],
                          B[bi >> 1][bi & 1], B[bi >> 1][(bi & 1) + 2]);
        }

        float* oh = out + ((size_t)head * Ss + sbase + c * 128) * Mm;
#pragma unroll
        for (int ah = 0; ah < 2; ah++) {
            int sr = sw + ah * 16 + gid;
            float inv0 = 1.f / (dens[cb * 128 + sr] + EPSV);
            float inv1 = 1.f / (dens[cb * 128 + sr + 8] + EPSV);
#pragma unroll
            for (int bi = 0; bi < 4; bi++) {
                int mc = m0 + bi * 8 + tig * 2;
                float2 r0 = make_float2(acc[ah][bi][0] * inv0, acc[ah][bi][1] * inv0);
                float2 r1 = make_float2(acc[ah][bi][2] * inv1, acc[ah][bi][3] * inv1);
                *(float2*)(oh + (size_t)sr * Mm + mc) = r0;
                *(float2*)(oh + (size_t)(sr + 8) * Mm + mc) = r1;
            }
        }
    }
}

// ---------------------------------------------------------------------------
extern "C" void kernel_launch(void* const* d_in, const int* in_sizes, int n_in,
                              void* d_out, int out_size) {
    (void)in_sizes; (void)n_in;
    const float* q      = (const float*)d_in[0];
    const float* k      = (const float*)d_in[1];
    const float* v      = (const float*)d_in[2];
    const float* mask   = (const float*)d_in[3];
    const float* S_prev = (const float*)d_in[4];
    const float* z_prev = (const float*)d_in[5];
    float* out = (float*)d_out;

    cudaFuncSetAttribute(k_phase1, cudaFuncAttributeMaxDynamicSharedMemorySize,
                         P1_SMEM_BYTES);
    cudaFuncSetAttribute(k_phase2, cudaFuncAttributeMaxDynamicSharedMemorySize,
                         SM2_BYTES);

    const long N_OUT = (long)BH * Ss * Mm;
    const long N_ST  = (long)BH * Dd * Mm;
    const long N_ZT  = (long)BH * Dd * Ss;
    long osz = (long)out_size;
    float* ztp  = (osz >= N_OUT + N_ST + N_ZT) ? (out + N_OUT + N_ST) : (float*)0;
    float* outS = (osz >= N_OUT + N_ST) ? (out + N_OUT) : (float*)0;

    dim3 g1(2 * (Ss / P1_CHUNK), BH);   // (chunk, mhalf) pairs
    k_phase1<<<g1, 256, P1_SMEM_BYTES>>>(k, v, mask, z_prev, ztp);

    dim3 gt(Dd / 32, Mm / 32, BH);
    k_transS<<<gt, dim3(32, 8)>>>(S_prev, z_prev, outS);

    dim3 g2(Ss / SQT, BH);
    k_phase2<<<g2, 512, SM2_BYTES>>>(q, out);
}

// round 16
// speedup vs baseline: 1.0694x; 1.0694x over previous
#include <cuda_runtime.h>
#include <cuda_fp16.h>
#include <cstdint>
#include <math.h>

#define Bq 4
#define Hh 16
#define Ss 4096
#define Dd 128
#define Mm 128
#define BH (Bq*Hh)
#define EPSV 1e-6f

// Scratch (zero at first load; k_zero re-zeroes g_S/g_w each execution)
__device__ float g_S [BH*Dd*Mm];  // S accumulation (WITHOUT S_prev), zero-based
__device__ float g_w [BH*Dd];     // sum_s phi(k)[s,d] accumulation, zero-based

__device__ __forceinline__ float phi(float x) {
    return x > 0.f ? x + 1.f : expf(x);
}
__device__ __forceinline__ unsigned packh2(float lo, float hi) {
    unsigned r;
    asm("cvt.rn.f16x2.f32 %0, %1, %2;" : "=r"(r) : "f"(hi), "f"(lo));
    return r;
}
__device__ __forceinline__ unsigned s2u(const void* p) {
    unsigned a;
    asm("{ .reg .u64 t; cvta.to.shared.u64 t, %1; cvt.u32.u64 %0, t; }"
        : "=r"(a) : "l"(p));
    return a;
}
__device__ __forceinline__ void mma16(float* c, const unsigned* a,
                                      unsigned b0, unsigned b1) {
    asm volatile(
        "mma.sync.aligned.m16n8k16.row.col.f32.f16.f16.f32 "
        "{%0,%1,%2,%3}, {%4,%5,%6,%7}, {%8,%9}, {%0,%1,%2,%3};"
        : "+f"(c[0]), "+f"(c[1]), "+f"(c[2]), "+f"(c[3])
        : "r"(a[0]), "r"(a[1]), "r"(a[2]), "r"(a[3]), "r"(b0), "r"(b1));
}
__device__ __forceinline__ void ldsm4(unsigned* r, unsigned a) {
    asm volatile("ldmatrix.sync.aligned.m8n8.x4.shared.b16 {%0,%1,%2,%3}, [%4];"
        : "=r"(r[0]), "=r"(r[1]), "=r"(r[2]), "=r"(r[3]) : "r"(a));
}
__device__ __forceinline__ void ldsm4t(unsigned* r, unsigned a) {
    asm volatile("ldmatrix.sync.aligned.m8n8.x4.trans.shared.b16 {%0,%1,%2,%3}, [%4];"
        : "=r"(r[0]), "=r"(r[1]), "=r"(r[2]), "=r"(r[3]) : "r"(a));
}

// ---------------------------------------------------------------------------
// Kernel 1 (fp16 + ldmatrix.trans, 512 thr, single wave grid (2, BH)):
//   g_S += phi(k)^T v ; g_w += sum_s phi(k) ; fused z_t via smem read-back
// Tiles s-major [32 s][128 halves], pitch 68 words; identical hot loop to R14.
// ---------------------------------------------------------------------------
#define P1_CHUNK 2048
#define P1S 32
#define P1P 68
#define TW (P1S*P1P)                    // 2176 words per tile
#define P1NST (P1_CHUNK/P1S)            // 64
#define P1_SMEM_BYTES (4*TW*4)          // 34816 B

__global__ void __launch_bounds__(512, 1)
k_phase1(const float* __restrict__ kk, const float* __restrict__ vv,
         const float* __restrict__ mask, const float* __restrict__ z_prev,
         float* __restrict__ ztp) {
    extern __shared__ unsigned dyn1[];
    __shared__ float zps[Dd];
    __shared__ float ksum_sm[P1S][Dd];

    int head = blockIdx.y;
    int sbase = blockIdx.x * P1_CHUNK;
    int tid = threadIdx.x;
    int warp = tid >> 5, lane = tid & 31;
    int gid = lane >> 2, tig = lane & 3;
    int d0w = (warp >> 2) * 32;
    int m0w = (warp & 3) * 32;
    int srow = tid >> 4;
    int dcol = (tid & 15) * 8;

    if (tid < Dd) zps[tid] = z_prev[head * Dd + tid];

    int lrow = (lane & 7) + ((lane >> 4) & 1) * 8;
    int csel = ((lane >> 3) & 1) * 16;
    int aOffB = lrow * (P1P * 4) + d0w * 2 + csel;
    int bOffB = lrow * (P1P * 4) + m0w * 2 + csel;
    unsigned kbase[2] = { s2u(dyn1), s2u(dyn1 + 2 * TW) };
    unsigned vbase[2] = { s2u(dyn1 + TW), s2u(dyn1 + 3 * TW) };

    float kacc[8];
#pragma unroll
    for (int j = 0; j < 8; j++) kacc[j] = 0.f;
    float acc[2][4][4];
#pragma unroll
    for (int ah = 0; ah < 2; ah++)
#pragma unroll
        for (int bi = 0; bi < 4; bi++)
#pragma unroll
            for (int t = 0; t < 4; t++) acc[ah][bi][t] = 0.f;

    const float* kh = kk + (size_t)head * Ss * Dd;
    const float* vh = vv + (size_t)head * Ss * Mm;
    const float* mh = mask + (size_t)head * Ss;
    float* zth = ztp ? (ztp + (size_t)head * Dd * Ss) : (float*)0;

    float4 kA, kB, vA, vB; float mval;
    {
        int s = sbase + srow;
        kA = *(const float4*)(kh + (size_t)s * Dd + dcol);
        kB = *(const float4*)(kh + (size_t)s * Dd + dcol + 4);
        vA = *(const float4*)(vh + (size_t)s * Mm + dcol);
        vB = *(const float4*)(vh + (size_t)s * Mm + dcol + 4);
        mval = mh[s];
    }

    for (int t = 0; t < P1NST; t++) {
        int b = t & 1;
        unsigned* kb = dyn1 + b * 2 * TW;
        unsigned* vb = kb + TW;
        float kv[8], va[8];
        kv[0]=phi(kA.x)*mval; kv[1]=phi(kA.y)*mval; kv[2]=phi(kA.z)*mval; kv[3]=phi(kA.w)*mval;
        kv[4]=phi(kB.x)*mval; kv[5]=phi(kB.y)*mval; kv[6]=phi(kB.z)*mval; kv[7]=phi(kB.w)*mval;
        va[0]=vA.x*mval; va[1]=vA.y*mval; va[2]=vA.z*mval; va[3]=vA.w*mval;
        va[4]=vB.x*mval; va[5]=vB.y*mval; va[6]=vB.z*mval; va[7]=vB.w*mval;
#pragma unroll
        for (int j = 0; j < 8; j++) kacc[j] += kv[j];
        {
            uint4 kp = make_uint4(packh2(kv[0], kv[1]), packh2(kv[2], kv[3]),
                                  packh2(kv[4], kv[5]), packh2(kv[6], kv[7]));
            uint4 vp = make_uint4(packh2(va[0], va[1]), packh2(va[2], va[3]),
                                  packh2(va[4], va[5]), packh2(va[6], va[7]));
            *(uint4*)&kb[srow * P1P + (tid & 15) * 4] = kp;
            *(uint4*)&vb[srow * P1P + (tid & 15) * 4] = vp;
        }

        if (t + 1 < P1NST) {   // batched coalesced prefetch, hidden by MMA
            int sn = sbase + (t + 1) * P1S + srow;
            kA = *(const float4*)(kh + (size_t)sn * Dd + dcol);
            kB = *(const float4*)(kh + (size_t)sn * Dd + dcol + 4);
            vA = *(const float4*)(vh + (size_t)sn * Mm + dcol);
            vB = *(const float4*)(vh + (size_t)sn * Mm + dcol + 4);
            mval = mh[sn];
        }
        __syncthreads();

        // fused z_t: transposed smem read-back, coalesced STG.128
        if (zth) {
            int dz = tid >> 2, szb = (tid & 3) * 8;
            const __half* khp = (const __half*)kb;
            float zf[8]; float zp = zps[dz];
#pragma unroll
            for (int i = 0; i < 8; i++)
                zf[i] = __half2float(khp[(szb + i) * (P1P * 2) + dz]) + zp;
            float* zr = zth + (size_t)dz * Ss + sbase + t * P1S + szb;
            *(float4*)zr       = make_float4(zf[0], zf[1], zf[2], zf[3]);
            *(float4*)(zr + 4) = make_float4(zf[4], zf[5], zf[6], zf[7]);
        }

#pragma unroll
        for (int ks = 0; ks < 2; ks++) {
            int so = ks * 16 * P1P * 4;
            unsigned A0[4], A1[4], B0[4], B1[4];
            ldsm4t(A0, kbase[b] + aOffB + so);
            ldsm4t(A1, kbase[b] + aOffB + so + 32);
            ldsm4t(B0, vbase[b] + bOffB + so);
            ldsm4t(B1, vbase[b] + bOffB + so + 32);
#pragma unroll
            for (int ah = 0; ah < 2; ah++) {
                const unsigned* Aa = ah ? A1 : A0;
#pragma unroll
                for (int bi = 0; bi < 4; bi++) {
                    const unsigned* Bl = (bi >> 1) ? B1 : B0;
                    mma16(acc[ah][bi], Aa, Bl[bi & 1], Bl[(bi & 1) + 2]);
                }
            }
        }
    }

    float* Sg = g_S + (size_t)head * Dd * Mm;
#pragma unroll
    for (int ah = 0; ah < 2; ah++)
#pragma unroll
        for (int bi = 0; bi < 4; bi++) {
            int dr = d0w + ah * 16 + gid;
            int mc = m0w + bi * 8 + tig * 2;
            atomicAdd(&Sg[(size_t)dr * Mm + mc],       acc[ah][bi][0]);
            atomicAdd(&Sg[(size_t)dr * Mm + mc + 1],   acc[ah][bi][1]);
            atomicAdd(&Sg[(size_t)(dr+8) * Mm + mc],   acc[ah][bi][2]);
            atomicAdd(&Sg[(size_t)(dr+8) * Mm + mc+1], acc[ah][bi][3]);
        }

#pragma unroll
    for (int j = 0; j < 8; j++) ksum_sm[srow][dcol + j] = kacc[j];
    __syncthreads();
    if (tid < Dd) {
        float s = 0.f;
#pragma unroll 8
        for (int i = 0; i < P1S; i++) s += ksum_sm[i][tid];
        atomicAdd(&g_w[head * Dd + tid], s);
    }
}

// ---------------------------------------------------------------------------
// Kernel 2 (fp16 tensor): out = (phi(q) @ S_t) / (phi(q).w + eps)
// grid (2, BH), 512 thr. B tile staged DIRECTLY from g_S + S_prev in [d][m]
// layout, consumed via ldmatrix.trans (mirror of phase1's v path). w computed
// in prologue from g_w + Ss*z_prev.
// ---------------------------------------------------------------------------
#define SQT 2048
#define NCH (SQT/128)
#define P2RW 68
#define P2BW (128*P2RW)
#define OFF_WS   (3*P2BW)
#define OFF_DENS (OFF_WS + 128)
#define SM2_WORDS (OFF_DENS + 256)
#define SM2_BYTES (SM2_WORDS * 4)

__global__ void __launch_bounds__(512, 1)
k_phase2(const float* __restrict__ qq, const float* __restrict__ S_prev,
         const float* __restrict__ z_prev, float* __restrict__ out) {
    extern __shared__ unsigned sm2[];
    unsigned* Ab[2] = { sm2, sm2 + P2BW };
    unsigned* Bb = sm2 + 2 * P2BW;                 // [d rows][m halves]
    float* ws   = (float*)(sm2 + OFF_WS);
    float* dens = (float*)(sm2 + OFF_DENS);        // [2][128]

    int head = blockIdx.y;
    int sbase = blockIdx.x * SQT;
    int tid = threadIdx.x;
    int warp = tid >> 5, lane = tid & 31;
    int gid = lane >> 2, tig = lane & 3;
    int sw = (warp >> 2) * 32;
    int m0 = (warp & 3) * 32;

    const float* qh = qq + (size_t)head * Ss * Dd;
    const float* Sg = g_S + (size_t)head * Dd * Mm;
    const float* Sp = S_prev + (size_t)head * Dd * Mm;

    if (tid < 128)
        ws[tid] = g_w[head * Dd + tid] + (float)Ss * z_prev[head * Dd + tid];

    // stage B = S_t in [d][m]: row d = warp+16i, lane covers m = 4*lane
    {
        const float* sg = Sg + (size_t)warp * Mm + lane * 4;
        const float* sp = Sp + (size_t)warp * Mm + lane * 4;
#pragma unroll
        for (int i = 0; i < 8; i++) {
            float4 a4 = *(const float4*)(sg + (size_t)(16 * i) * Mm);
            float4 b4 = *(const float4*)(sp + (size_t)(16 * i) * Mm);
            float s0 = a4.x + b4.x, s1 = a4.y + b4.y;
            float s2 = a4.z + b4.z, s3 = a4.w + b4.w;
            int r = warp + 16 * i;
            unsigned* w = Bb + r * P2RW + lane * 2;
            w[0] = packh2(s0, s1);
            w[1] = packh2(s2, s3);
        }
    }
    __syncthreads();
    float4 wv4 = *(const float4*)(ws + lane * 4);

    // stage A chunk 0 + dens[0]
    {
        const float* qp = qh + (size_t)(sbase + warp) * Dd + lane * 4;
#pragma unroll
        for (int i = 0; i < 8; i++) {
            float4 qa = *(const float4*)(qp + (size_t)(16 * i) * Dd);
            float p0 = phi(qa.x), p1 = phi(qa.y), p2 = phi(qa.z), p3 = phi(qa.w);
            float ds = p0 * wv4.x + p1 * wv4.y + p2 * wv4.z + p3 * wv4.w;
            ds += __shfl_xor_sync(0xffffffffu, ds, 1);
            ds += __shfl_xor_sync(0xffffffffu, ds, 2);
            ds += __shfl_xor_sync(0xffffffffu, ds, 4);
            ds += __shfl_xor_sync(0xffffffffu, ds, 8);
            ds += __shfl_xor_sync(0xffffffffu, ds, 16);
            int r = warp + 16 * i;
            if (lane == 0) dens[r] = ds;
            unsigned* w = Ab[0] + r * P2RW + lane * 2;
            w[0] = packh2(p0, p1);
            w[1] = packh2(p2, p3);
        }
    }

    // A fragments: non-trans ldsm on [s][d]; B fragments: trans ldsm on [d][m]
    int sel = lane >> 3, lrow8 = lane & 7;
    int aOffB = 4 * ((sw + (sel & 1) * 8 + lrow8) * P2RW + (sel >> 1) * 4);
    int lrowT = (lane & 7) + ((lane >> 4) & 1) * 8;
    int cselT = ((lane >> 3) & 1) * 16;
    int bOffB = lrowT * (P2RW * 4) + m0 * 2 + cselT;
    unsigned aBase[2] = { s2u(Ab[0]), s2u(Ab[1]) };
    unsigned bBase = s2u(Bb);
    const int ROW16 = 16 * P2RW * 4;

    for (int c = 0; c < NCH; c++) {
        int cb = c & 1, nb = cb ^ 1;
        bool more = (c + 1 < NCH);

        float4 qn[8];
        if (more) {
            const float* qp = qh + (size_t)(sbase + (c + 1) * 128 + warp) * Dd + lane * 4;
#pragma unroll
            for (int i = 0; i < 8; i++)
                qn[i] = *(const float4*)(qp + (size_t)(16 * i) * Dd);
        }
        __syncthreads();

        float acc[2][4][4];
#pragma unroll
        for (int ah = 0; ah < 2; ah++)
#pragma unroll
            for (int bi = 0; bi < 4; bi++)
#pragma unroll
                for (int t = 0; t < 4; t++) acc[ah][bi][t] = 0.f;

#pragma unroll
        for (int i = 0; i < 8; i++) {          // 8 k16 steps over d=128
            if (more && i >= 4) {
#pragma unroll
                for (int h = 0; h < 2; h++) {
                    int j = (i - 4) * 2 + h;
                    float p0 = phi(qn[j].x), p1 = phi(qn[j].y),
                          p2 = phi(qn[j].z), p3 = phi(qn[j].w);
                    float ds = p0 * wv4.x + p1 * wv4.y + p2 * wv4.z + p3 * wv4.w;
                    ds += __shfl_xor_sync(0xffffffffu, ds, 1);
                    ds += __shfl_xor_sync(0xffffffffu, ds, 2);
                    ds += __shfl_xor_sync(0xffffffffu, ds, 4);
                    ds += __shfl_xor_sync(0xffffffffu, ds, 8);
                    ds += __shfl_xor_sync(0xffffffffu, ds, 16);
                    int r = warp + 16 * j;
                    if (lane == 0) dens[nb * 128 + r] = ds;
                    unsigned* w = Ab[nb] + r * P2RW + lane * 2;
                    w[0] = packh2(p0, p1);
                    w[1] = packh2(p2, p3);
                }
            }
            unsigned A[2][4], B0[4], B1[4];
            ldsm4(A[0], aBase[cb] + aOffB + i * 32);
            ldsm4(A[1], aBase[cb] + aOffB + ROW16 + i * 32);
            ldsm4t(B0, bBase + bOffB + i * ROW16);        // d rows 16i..16i+15
            ldsm4t(B1, bBase + bOffB + i * ROW16 + 32);   // m+16
#pragma unroll
            for (int ah = 0; ah < 2; ah++)
#pragma unroll
                for (int bi = 0; bi < 4; bi++) {
                    const unsigned* Bl = (bi >> 1) ? B1 : B0;
                    mma16(acc[ah][bi], A[ah], Bl[bi & 1], Bl[(bi & 1) + 2]);
                }
        }

        float* oh = out + ((size_t)head * Ss + sbase + c * 128) * Mm;
#pragma unroll
        for (int ah = 0; ah < 2; ah++) {
            int sr = sw + ah * 16 + gid;
            float inv0 = 1.f / (dens[cb * 128 + sr] + EPSV);
            float inv1 = 1.f / (dens[cb * 128 + sr + 8] + EPSV);
#pragma unroll
            for (int bi = 0; bi < 4; bi++) {
                int mc = m0 + bi * 8 + tig * 2;
                float2 r0 = make_float2(acc[ah][bi][0] * inv0, acc[ah][bi][1] * inv0);
                float2 r1 = make_float2(acc[ah][bi][2] * inv1, acc[ah][bi][3] * inv1);
                *(float2*)(oh + (size_t)sr * Mm + mc) = r0;
                *(float2*)(oh + (size_t)(sr + 8) * Mm + mc) = r1;
            }
        }
    }
}

// ---------------------------------------------------------------------------
// Kernel 3 (slim): outS = g_S + S_prev (if requested); re-zero g_S and g_w.
// Runs AFTER k_phase2 (which reads g_S/g_w).
// ---------------------------------------------------------------------------
__global__ void k_finish(const float* __restrict__ S_prev,
                         float* __restrict__ outS) {
    int head = blockIdx.x;
    float* Sg = g_S + (size_t)head * Dd * Mm;
    const float* Sp = S_prev + (size_t)head * Dd * Mm;
    if (outS) {
        float* So = outS + (size_t)head * Dd * Mm;
        for (int i = threadIdx.x; i < Dd * Mm; i += blockDim.x) {
            So[i] = Sg[i] + Sp[i];
            Sg[i] = 0.f;
        }
    } else {
        for (int i = threadIdx.x; i < Dd * Mm; i += blockDim.x)
            Sg[i] = 0.f;
    }
    if (threadIdx.x < Dd) g_w[head * Dd + threadIdx.x] = 0.f;
}

// ---------------------------------------------------------------------------
extern "C" void kernel_launch(void* const* d_in, const int* in_sizes, int n_in,
                              void* d_out, int out_size) {
    (void)in_sizes; (void)n_in;
    const float* q      = (const float*)d_in[0];
    const float* k      = (const float*)d_in[1];
    const float* v      = (const float*)d_in[2];
    const float* mask   = (const float*)d_in[3];
    const float* S_prev = (const float*)d_in[4];
    const float* z_prev = (const float*)d_in[5];
    float* out = (float*)d_out;

    cudaFuncSetAttribute(k_phase1, cudaFuncAttributeMaxDynamicSharedMemorySize,
                         P1_SMEM_BYTES);
    cudaFuncSetAttribute(k_phase2, cudaFuncAttributeMaxDynamicSharedMemorySize,
                         SM2_BYTES);

    const long N_OUT = (long)BH * Ss * Mm;
    const long N_ST  = (long)BH * Dd * Mm;
    const long N_ZT  = (long)BH * Dd * Ss;
    long osz = (long)out_size;
    float* ztp  = (osz >= N_OUT + N_ST + N_ZT) ? (out + N_OUT + N_ST) : (float*)0;
    float* outS = (osz >= N_OUT + N_ST) ? (out + N_OUT) : (float*)0;

    dim3 g1(Ss / P1_CHUNK, BH);   // (2, 64) single wave
    k_phase1<<<g1, 512, P1_SMEM_BYTES>>>(k, v, mask, z_prev, ztp);

    dim3 g2(Ss / SQT, BH);        // (2, 64) single wave
    k_phase2<<<g2, 512, SM2_BYTES>>>(q, S_prev, z_prev, out);

    k_finish<<<BH, 256>>>(S_prev, outS);
}

// round 17
// speedup vs baseline: 1.2006x; 1.1227x over previous
#include <cuda_runtime.h>
#include <cuda_fp16.h>
#include <cstdint>
#include <math.h>

#define Bq 4
#define Hh 16
#define Ss 4096
#define Dd 128
#define Mm 128
#define BH (Bq*Hh)
#define EPSV 1e-6f

// Scratch (zero at first load; every execution re-zeroes g_S/g_w in k_transS)
__device__ float g_S [BH*Dd*Mm];  // S accumulation (WITHOUT S_prev), zero-based
__device__ float g_ST[BH*Dd*Mm];  // S_t transposed [BH, M, D] (fp32)
__device__ float g_w [BH*Dd];     // sum_s phi(k)[s,d] accumulation, zero-based
__device__ float g_w2[BH*Dd];     // final w[d] = Ss*z_prev[d] + g_w[d]

__device__ __forceinline__ float phi(float x) {
    return x > 0.f ? x + 1.f : expf(x);
}
__device__ __forceinline__ unsigned packh2(float lo, float hi) {
    unsigned r;
    asm("cvt.rn.f16x2.f32 %0, %1, %2;" : "=r"(r) : "f"(hi), "f"(lo));
    return r;
}
__device__ __forceinline__ unsigned s2u(const void* p) {
    unsigned a;
    asm("{ .reg .u64 t; cvta.to.shared.u64 t, %1; cvt.u32.u64 %0, t; }"
        : "=r"(a) : "l"(p));
    return a;
}
__device__ __forceinline__ void mma16(float* c, const unsigned* a,
                                      unsigned b0, unsigned b1) {
    asm volatile(
        "mma.sync.aligned.m16n8k16.row.col.f32.f16.f16.f32 "
        "{%0,%1,%2,%3}, {%4,%5,%6,%7}, {%8,%9}, {%0,%1,%2,%3};"
        : "+f"(c[0]), "+f"(c[1]), "+f"(c[2]), "+f"(c[3])
        : "r"(a[0]), "r"(a[1]), "r"(a[2]), "r"(a[3]), "r"(b0), "r"(b1));
}
__device__ __forceinline__ void ldsm4(unsigned* r, unsigned a) {
    asm volatile("ldmatrix.sync.aligned.m8n8.x4.shared.b16 {%0,%1,%2,%3}, [%4];"
        : "=r"(r[0]), "=r"(r[1]), "=r"(r[2]), "=r"(r[3]) : "r"(a));
}
__device__ __forceinline__ void ldsm4t(unsigned* r, unsigned a) {
    asm volatile("ldmatrix.sync.aligned.m8n8.x4.trans.shared.b16 {%0,%1,%2,%3}, [%4];"
        : "=r"(r[0]), "=r"(r[1]), "=r"(r[2]), "=r"(r[3]) : "r"(a));
}

// ---------------------------------------------------------------------------
// Kernel 1 (fp16 + ldmatrix.trans, 512 thr, single wave grid (2, BH)):
//   g_S += phi(k)^T v ; g_w += sum_s phi(k) ; fused z_t via smem read-back
// Tiles s-major [32 s][128 halves], pitch 68 words. (R16 phase1, measured 135us)
// ---------------------------------------------------------------------------
#define P1_CHUNK 2048
#define P1S 32
#define P1P 68
#define TW (P1S*P1P)                    // 2176 words per tile
#define P1NST (P1_CHUNK/P1S)            // 64
#define P1_SMEM_BYTES (4*TW*4)          // 34816 B

__global__ void __launch_bounds__(512, 1)
k_phase1(const float* __restrict__ kk, const float* __restrict__ vv,
         const float* __restrict__ mask, const float* __restrict__ z_prev,
         float* __restrict__ ztp) {
    extern __shared__ unsigned dyn1[];
    __shared__ float zps[Dd];
    __shared__ float ksum_sm[P1S][Dd];

    int head = blockIdx.y;
    int sbase = blockIdx.x * P1_CHUNK;
    int tid = threadIdx.x;
    int warp = tid >> 5, lane = tid & 31;
    int gid = lane >> 2, tig = lane & 3;
    int d0w = (warp >> 2) * 32;
    int m0w = (warp & 3) * 32;
    int srow = tid >> 4;
    int dcol = (tid & 15) * 8;

    if (tid < Dd) zps[tid] = z_prev[head * Dd + tid];

    int lrow = (lane & 7) + ((lane >> 4) & 1) * 8;
    int csel = ((lane >> 3) & 1) * 16;
    int aOffB = lrow * (P1P * 4) + d0w * 2 + csel;
    int bOffB = lrow * (P1P * 4) + m0w * 2 + csel;
    unsigned kbase[2] = { s2u(dyn1), s2u(dyn1 + 2 * TW) };
    unsigned vbase[2] = { s2u(dyn1 + TW), s2u(dyn1 + 3 * TW) };

    float kacc[8];
#pragma unroll
    for (int j = 0; j < 8; j++) kacc[j] = 0.f;
    float acc[2][4][4];
#pragma unroll
    for (int ah = 0; ah < 2; ah++)
#pragma unroll
        for (int bi = 0; bi < 4; bi++)
#pragma unroll
            for (int t = 0; t < 4; t++) acc[ah][bi][t] = 0.f;

    const float* kh = kk + (size_t)head * Ss * Dd;
    const float* vh = vv + (size_t)head * Ss * Mm;
    const float* mh = mask + (size_t)head * Ss;
    float* zth = ztp ? (ztp + (size_t)head * Dd * Ss) : (float*)0;

    float4 kA, kB, vA, vB; float mval;
    {
        int s = sbase + srow;
        kA = *(const float4*)(kh + (size_t)s * Dd + dcol);
        kB = *(const float4*)(kh + (size_t)s * Dd + dcol + 4);
        vA = *(const float4*)(vh + (size_t)s * Mm + dcol);
        vB = *(const float4*)(vh + (size_t)s * Mm + dcol + 4);
        mval = mh[s];
    }

    for (int t = 0; t < P1NST; t++) {
        int b = t & 1;
        unsigned* kb = dyn1 + b * 2 * TW;
        unsigned* vb = kb + TW;
        float kv[8], va[8];
        kv[0]=phi(kA.x)*mval; kv[1]=phi(kA.y)*mval; kv[2]=phi(kA.z)*mval; kv[3]=phi(kA.w)*mval;
        kv[4]=phi(kB.x)*mval; kv[5]=phi(kB.y)*mval; kv[6]=phi(kB.z)*mval; kv[7]=phi(kB.w)*mval;
        va[0]=vA.x*mval; va[1]=vA.y*mval; va[2]=vA.z*mval; va[3]=vA.w*mval;
        va[4]=vB.x*mval; va[5]=vB.y*mval; va[6]=vB.z*mval; va[7]=vB.w*mval;
#pragma unroll
        for (int j = 0; j < 8; j++) kacc[j] += kv[j];
        {
            uint4 kp = make_uint4(packh2(kv[0], kv[1]), packh2(kv[2], kv[3]),
                                  packh2(kv[4], kv[5]), packh2(kv[6], kv[7]));
            uint4 vp = make_uint4(packh2(va[0], va[1]), packh2(va[2], va[3]),
                                  packh2(va[4], va[5]), packh2(va[6], va[7]));
            *(uint4*)&kb[srow * P1P + (tid & 15) * 4] = kp;
            *(uint4*)&vb[srow * P1P + (tid & 15) * 4] = vp;
        }

        if (t + 1 < P1NST) {   // batched coalesced prefetch, hidden by MMA
            int sn = sbase + (t + 1) * P1S + srow;
            kA = *(const float4*)(kh + (size_t)sn * Dd + dcol);
            kB = *(const float4*)(kh + (size_t)sn * Dd + dcol + 4);
            vA = *(const float4*)(vh + (size_t)sn * Mm + dcol);
            vB = *(const float4*)(vh + (size_t)sn * Mm + dcol + 4);
            mval = mh[sn];
        }
        __syncthreads();

        // fused z_t: transposed smem read-back, coalesced STG.128
        if (zth) {
            int dz = tid >> 2, szb = (tid & 3) * 8;
            const __half* khp = (const __half*)kb;
            float zf[8]; float zp = zps[dz];
#pragma unroll
            for (int i = 0; i < 8; i++)
                zf[i] = __half2float(khp[(szb + i) * (P1P * 2) + dz]) + zp;
            float* zr = zth + (size_t)dz * Ss + sbase + t * P1S + szb;
            *(float4*)zr       = make_float4(zf[0], zf[1], zf[2], zf[3]);
            *(float4*)(zr + 4) = make_float4(zf[4], zf[5], zf[6], zf[7]);
        }

#pragma unroll
        for (int ks = 0; ks < 2; ks++) {
            int so = ks * 16 * P1P * 4;
            unsigned A0[4], A1[4], B0[4], B1[4];
            ldsm4t(A0, kbase[b] + aOffB + so);
            ldsm4t(A1, kbase[b] + aOffB + so + 32);   // d+16
            ldsm4t(B0, vbase[b] + bOffB + so);
            ldsm4t(B1, vbase[b] + bOffB + so + 32);   // m+16
#pragma unroll
            for (int ah = 0; ah < 2; ah++) {
                const unsigned* Aa = ah ? A1 : A0;
#pragma unroll
                for (int bi = 0; bi < 4; bi++) {
                    const unsigned* Bl = (bi >> 1) ? B1 : B0;
                    mma16(acc[ah][bi], Aa, Bl[bi & 1], Bl[(bi & 1) + 2]);
                }
            }
        }
    }

    float* Sg = g_S + (size_t)head * Dd * Mm;
#pragma unroll
    for (int ah = 0; ah < 2; ah++)
#pragma unroll
        for (int bi = 0; bi < 4; bi++) {
            int dr = d0w + ah * 16 + gid;
            int mc = m0w + bi * 8 + tig * 2;
            atomicAdd(&Sg[(size_t)dr * Mm + mc],       acc[ah][bi][0]);
            atomicAdd(&Sg[(size_t)dr * Mm + mc + 1],   acc[ah][bi][1]);
            atomicAdd(&Sg[(size_t)(dr+8) * Mm + mc],   acc[ah][bi][2]);
            atomicAdd(&Sg[(size_t)(dr+8) * Mm + mc+1], acc[ah][bi][3]);
        }

    // ksum: smem column reduction, one atomic per d per CTA
#pragma unroll
    for (int j = 0; j < 8; j++) ksum_sm[srow][dcol + j] = kacc[j];
    __syncthreads();
    if (tid < Dd) {
        float s = 0.f;
#pragma unroll 8
        for (int i = 0; i < P1S; i++) s += ksum_sm[i][tid];
        atomicAdd(&g_w[head * Dd + tid], s);
    }
}

// ---------------------------------------------------------------------------
// Kernel 1b (R14): S_t = g_S + S_prev -> (outS copy, g_ST transposed fp32),
// g_w2 = g_w + Ss*z_prev; re-zero g_S/g_w for next replay.
// ---------------------------------------------------------------------------
__global__ void k_transS(const float* __restrict__ S_prev,
                         const float* __restrict__ z_prev,
                         float* __restrict__ outS) {
    __shared__ float tile[32][33];
    int head = blockIdx.z;
    int db = blockIdx.x * 32, mb = blockIdx.y * 32;
    int tx = threadIdx.x, ty = threadIdx.y;
    float* Sg = g_S + (size_t)head * Dd * Mm;
    const float* Sp = S_prev + (size_t)head * Dd * Mm;
    float* STg = g_ST + (size_t)head * Dd * Mm;
    float* So = outS ? (outS + (size_t)head * Dd * Mm) : (float*)0;
    for (int r = ty; r < 32; r += 8) {
        size_t idx = (size_t)(db + r) * Mm + mb + tx;
        float val = Sg[idx] + Sp[idx];
        tile[r][tx] = val;
        if (So) So[idx] = val;
        Sg[idx] = 0.f;
    }
    if (blockIdx.x == 0 && blockIdx.y == 0) {
        int tid = ty * 32 + tx;
        if (tid < Dd) {
            g_w2[head * Dd + tid] = g_w[head * Dd + tid]
                                  + (float)Ss * z_prev[head * Dd + tid];
            g_w[head * Dd + tid] = 0.f;
        }
    }
    __syncthreads();
    for (int r = ty; r < 32; r += 8)
        STg[(size_t)(mb + r) * Dd + db + tx] = tile[tx][r];
}

// ---------------------------------------------------------------------------
// Kernel 2 (R14 fp16 tensor): out = (phi(q) @ S_t) / (phi(q).w + eps)
// ---------------------------------------------------------------------------
#define SQT 2048
#define NCH (SQT/128)
#define P2RW 68
#define P2BW (128*P2RW)
#define OFF_WS   (3*P2BW)
#define OFF_DENS (OFF_WS + 128)
#define SM2_WORDS (OFF_DENS + 256)
#define SM2_BYTES (SM2_WORDS * 4)

__global__ void __launch_bounds__(512, 1)
k_phase2(const float* __restrict__ qq, float* __restrict__ out) {
    extern __shared__ unsigned sm2[];
    unsigned* Ab[2] = { sm2, sm2 + P2BW };
    unsigned* Bb = sm2 + 2 * P2BW;
    float* ws   = (float*)(sm2 + OFF_WS);
    float* dens = (float*)(sm2 + OFF_DENS);   // [2][128]

    int head = blockIdx.y;
    int sbase = blockIdx.x * SQT;
    int tid = threadIdx.x;
    int warp = tid >> 5, lane = tid & 31;
    int gid = lane >> 2, tig = lane & 3;
    int sw = (warp >> 2) * 32;
    int m0 = (warp & 3) * 32;

    const float* qh  = qq + (size_t)head * Ss * Dd;
    const float* STg = g_ST + (size_t)head * Dd * Mm;

    if (tid < 128) ws[tid] = g_w2[head * Dd + tid];
    {
        const float* bp = STg + (size_t)warp * Dd + lane * 4;
#pragma unroll
        for (int i = 0; i < 8; i++) {
            float4 t4 = *(const float4*)(bp + (size_t)(16 * i) * Dd);
            int r = warp + 16 * i;
            unsigned* w = Bb + r * P2RW + lane * 2;
            w[0] = packh2(t4.x, t4.y);
            w[1] = packh2(t4.z, t4.w);
        }
    }
    __syncthreads();
    float4 wv4 = *(const float4*)(ws + lane * 4);

    {
        const float* qp = qh + (size_t)(sbase + warp) * Dd + lane * 4;
#pragma unroll
        for (int i = 0; i < 8; i++) {
            float4 qa = *(const float4*)(qp + (size_t)(16 * i) * Dd);
            float p0 = phi(qa.x), p1 = phi(qa.y), p2 = phi(qa.z), p3 = phi(qa.w);
            float ds = p0 * wv4.x + p1 * wv4.y + p2 * wv4.z + p3 * wv4.w;
            ds += __shfl_xor_sync(0xffffffffu, ds, 1);
            ds += __shfl_xor_sync(0xffffffffu, ds, 2);
            ds += __shfl_xor_sync(0xffffffffu, ds, 4);
            ds += __shfl_xor_sync(0xffffffffu, ds, 8);
            ds += __shfl_xor_sync(0xffffffffu, ds, 16);
            int r = warp + 16 * i;
            if (lane == 0) dens[r] = ds;
            unsigned* w = Ab[0] + r * P2RW + lane * 2;
            w[0] = packh2(p0, p1);
            w[1] = packh2(p2, p3);
        }
    }

    int sel = lane >> 3, lrow = lane & 7;
    int aOffB = 4 * ((sw + (sel & 1) * 8 + lrow) * P2RW + (sel >> 1) * 4);
    int bOffB = 4 * ((m0 + (sel & 1) * 8 + lrow) * P2RW + (sel >> 1) * 4);
    unsigned aBase[2] = { s2u(Ab[0]), s2u(Ab[1]) };
    unsigned bBase = s2u(Bb);
    const int ROW16 = 16 * P2RW * 4;

    for (int c = 0; c < NCH; c++) {
        int cb = c & 1, nb = cb ^ 1;
        bool more = (c + 1 < NCH);

        float4 qn[8];
        if (more) {
            const float* qp = qh + (size_t)(sbase + (c + 1) * 128 + warp) * Dd + lane * 4;
#pragma unroll
            for (int i = 0; i < 8; i++)
                qn[i] = *(const float4*)(qp + (size_t)(16 * i) * Dd);
        }
        __syncthreads();

        float acc[2][4][4];
#pragma unroll
        for (int ah = 0; ah < 2; ah++)
#pragma unroll
            for (int bi = 0; bi < 4; bi++)
#pragma unroll
                for (int t = 0; t < 4; t++) acc[ah][bi][t] = 0.f;

#pragma unroll
        for (int i = 0; i < 8; i++) {
            if (more && i >= 4) {
#pragma unroll
                for (int h = 0; h < 2; h++) {
                    int j = (i - 4) * 2 + h;
                    float p0 = phi(qn[j].x), p1 = phi(qn[j].y),
                          p2 = phi(qn[j].z), p3 = phi(qn[j].w);
                    float ds = p0 * wv4.x + p1 * wv4.y + p2 * wv4.z + p3 * wv4.w;
                    ds += __shfl_xor_sync(0xffffffffu, ds, 1);
                    ds += __shfl_xor_sync(0xffffffffu, ds, 2);
                    ds += __shfl_xor_sync(0xffffffffu, ds, 4);
                    ds += __shfl_xor_sync(0xffffffffu, ds, 8);
                    ds += __shfl_xor_sync(0xffffffffu, ds, 16);
                    int r = warp + 16 * j;
                    if (lane == 0) dens[nb * 128 + r] = ds;
                    unsigned* w = Ab[nb] + r * P2RW + lane * 2;
                    w[0] = packh2(p0, p1);
                    w[1] = packh2(p2, p3);
                }
            }
            unsigned A[2][4], B[2][4];
            ldsm4(A[0], aBase[cb] + aOffB + i * 32);
            ldsm4(A[1], aBase[cb] + aOffB + ROW16 + i * 32);
            ldsm4(B[0], bBase + bOffB + i * 32);
            ldsm4(B[1], bBase + bOffB + ROW16 + i * 32);
#pragma unroll
            for (int ah = 0; ah < 2; ah++)
#pragma unroll
                for (int bi = 0; bi < 4; bi++)
                    mma16(acc[ah][bi], A[ah],
                          B[bi >> 1][bi & 1], B[bi >> 1][(bi & 1) + 2]);
        }

        float* oh = out + ((size_t)head * Ss + sbase + c * 128) * Mm;
#pragma unroll
        for (int ah = 0; ah < 2; ah++) {
            int sr = sw + ah * 16 + gid;
            float inv0 = 1.f / (dens[cb * 128 + sr] + EPSV);
            float inv1 = 1.f / (dens[cb * 128 + sr + 8] + EPSV);
#pragma unroll
            for (int bi = 0; bi < 4; bi++) {
                int mc = m0 + bi * 8 + tig * 2;
                float2 r0 = make_float2(acc[ah][bi][0] * inv0, acc[ah][bi][1] * inv0);
                float2 r1 = make_float2(acc[ah][bi][2] * inv1, acc[ah][bi][3] * inv1);
                *(float2*)(oh + (size_t)sr * Mm + mc) = r0;
                *(float2*)(oh + (size_t)(sr + 8) * Mm + mc) = r1;
            }
        }
    }
}

// ---------------------------------------------------------------------------
extern "C" void kernel_launch(void* const* d_in, const int* in_sizes, int n_in,
                              void* d_out, int out_size) {
    (void)in_sizes; (void)n_in;
    const float* q      = (const float*)d_in[0];
    const float* k      = (const float*)d_in[1];
    const float* v      = (const float*)d_in[2];
    const float* mask   = (const float*)d_in[3];
    const float* S_prev = (const float*)d_in[4];
    const float* z_prev = (const float*)d_in[5];
    float* out = (float*)d_out;

    cudaFuncSetAttribute(k_phase1, cudaFuncAttributeMaxDynamicSharedMemorySize,
                         P1_SMEM_BYTES);
    cudaFuncSetAttribute(k_phase2, cudaFuncAttributeMaxDynamicSharedMemorySize,
                         SM2_BYTES);

    const long N_OUT = (long)BH * Ss * Mm;
    const long N_ST  = (long)BH * Dd * Mm;
    const long N_ZT  = (long)BH * Dd * Ss;
    long osz = (long)out_size;
    float* ztp  = (osz >= N_OUT + N_ST + N_ZT) ? (out + N_OUT + N_ST) : (float*)0;
    float* outS = (osz >= N_OUT + N_ST) ? (out + N_OUT) : (float*)0;

    dim3 g1(Ss / P1_CHUNK, BH);   // (2, 64) single wave
    k_phase1<<<g1, 512, P1_SMEM_BYTES>>>(k, v, mask, z_prev, ztp);

    dim3 gt(Dd / 32, Mm / 32, BH);
    k_transS<<<gt, dim3(32, 8)>>>(S_prev, z_prev, outS);

    dim3 g2(Ss / SQT, BH);        // (2, 64) single wave
    k_phase2<<<g2, 512, SM2_BYTES>>>(q, out);
}